// round 12
// baseline (speedup 1.0000x reference)
#include <cuda_runtime.h>
#include <cuda_fp16.h>
#include <mma.h>
#include <math.h>

using namespace nvcuda;

#define NN 50000
#define EE 800000
#define ET (EE + NN)
#define FIN 128
#define HID 64
#define H1 8
#define C1 (H1 * HID)   // 512
#define GG 64
#define NEG_SLOPE 0.2f
#define EPS 1e-16f
#define SCAN_B 1024
#define SCAN_NB ((NN + SCAN_B - 1) / SCAN_B)   // 49
#define G1_BLOCKS 1564          // 4 x 391
#define G1_HALF 782
#define CVTX_BLOCKS ((NN * FIN / 8 + 1023) / 1024)   // 782
#define SCAT_BLOCKS ((ET + 255) / 256)               // 3321
#define SORT_BLOCKS ((NN + 255) / 256)               // 196

// ---------------- scratch (device globals; no allocations allowed) ----------
__device__ __half g_xh[(size_t)NN * FIN];
__device__ __half g_w1h[FIN * C1];
__device__ __half g_w2h[C1 * HID];
__device__ __half g_h1h[(size_t)NN * C1];
__device__ __half g_hah[(size_t)NN * C1];
__device__ __half g_h2h[(size_t)NN * HID];
__device__ float  g_as1[NN * H1];
__device__ float  g_ad1[NN * H1];
__device__ float  g_as2[NN];
__device__ float  g_ad2[NN];
__device__ float  g_out2[NN * HID];
__device__ int    g_deg[NN];     // zeroed at load; re-zeroed by scan_a each call
__device__ int    g_fill[NN];    // zeroed at load; re-zeroed by sortseg each call
__device__ int    g_rowptr[NN + 1];
__device__ int    g_part[64];
__device__ int    g_esrc[ET];

// ---------------- CSR: count ----------------
__global__ void k_count(const int* __restrict__ ei) {
    int i = blockIdx.x * blockDim.x + threadIdx.x;
    if (i >= ET) return;
    int dst = (i < EE) ? ei[EE + i] : (i - EE);
    atomicAdd(&g_deg[dst], 1);
}

// ---------------- scan_a (+re-zero g_deg) || cvtx --------------------------
__global__ void k_scanA_cvtx(const float* __restrict__ x) {
    __shared__ int s[SCAN_B];
    if (blockIdx.x < SCAN_NB) {
        int i = blockIdx.x * SCAN_B + threadIdx.x;
        int v = (i < NN) ? g_deg[i] : 0;
        if (i < NN) g_deg[i] = 0;               // restore invariant for next call
        s[threadIdx.x] = v;
        __syncthreads();
        #pragma unroll
        for (int off = 1; off < SCAN_B; off <<= 1) {
            int t = (threadIdx.x >= off) ? s[threadIdx.x - off] : 0;
            __syncthreads();
            s[threadIdx.x] += t;
            __syncthreads();
        }
        if (i < NN) g_rowptr[i] = s[threadIdx.x] - v;
        if (threadIdx.x == SCAN_B - 1) g_part[blockIdx.x] = s[SCAN_B - 1];
    } else {
        int i = (blockIdx.x - SCAN_NB) * 1024 + threadIdx.x;
        if (i >= NN * FIN / 8) return;
        const float4* p = (const float4*)x + (size_t)i * 2;
        float4 a = p[0], b = p[1];
        union { uint4 u; __half2 h[4]; } pk;
        pk.h[0] = __floats2half2_rn(a.x, a.y);
        pk.h[1] = __floats2half2_rn(a.z, a.w);
        pk.h[2] = __floats2half2_rn(b.x, b.y);
        pk.h[3] = __floats2half2_rn(b.z, b.w);
        ((uint4*)g_xh)[i] = pk.u;
    }
}

// ---------------- scan_b || cvtw --------------------------------------------
__global__ void k_scanB_cvtw(const float* __restrict__ W1, const float* __restrict__ W2) {
    if (blockIdx.x == 0) {
        if (threadIdx.x >= 32) return;
        int lane = threadIdx.x;
        int v0 = (lane < SCAN_NB) ? g_part[lane] : 0;
        int v1 = (lane + 32 < SCAN_NB) ? g_part[lane + 32] : 0;
        int x0 = v0;
        #pragma unroll
        for (int off = 1; off < 32; off <<= 1) {
            int t = __shfl_up_sync(0xffffffffu, x0, off);
            if (lane >= off) x0 += t;
        }
        int total0 = __shfl_sync(0xffffffffu, x0, 31);
        int x1 = v1;
        #pragma unroll
        for (int off = 1; off < 32; off <<= 1) {
            int t = __shfl_up_sync(0xffffffffu, x1, off);
            if (lane >= off) x1 += t;
        }
        x1 += total0;
        if (lane < SCAN_NB) g_part[lane] = x0 - v0;
        if (lane + 32 < SCAN_NB) g_part[lane + 32] = x1 - v1;
        if (lane == 31) g_rowptr[NN] = x1;
    } else {
        int i = (blockIdx.x - 1) * 256 + threadIdx.x;
        const int n1 = FIN * C1 / 8;
        const int n2 = C1 * HID / 8;
        if (i >= n1 + n2) return;
        const float* src; __half* dst; int j;
        if (i < n1) { src = W1; dst = g_w1h; j = i; }
        else        { src = W2; dst = g_w2h; j = i - n1; }
        const float4* p = (const float4*)src + (size_t)j * 2;
        float4 a = p[0], b = p[1];
        union { uint4 u; __half2 h[4]; } pk;
        pk.h[0] = __floats2half2_rn(a.x, a.y);
        pk.h[1] = __floats2half2_rn(a.z, a.w);
        pk.h[2] = __floats2half2_rn(b.x, b.y);
        pk.h[3] = __floats2half2_rn(b.z, b.w);
        ((uint4*)dst)[j] = pk.u;
    }
}

__global__ void k_scan_c() {
    int i = blockIdx.x * SCAN_B + threadIdx.x;
    if (i < NN) g_rowptr[i] += g_part[blockIdx.x];
}

// ---------------- GEMM1 body (tensor core) + att scores --------------------
__device__ __forceinline__ void gemm1_body(int g, char* dsm,
                                           const float* __restrict__ att_s,
                                           const float* __restrict__ att_d) {
    __half* As = (__half*)dsm;              // [128][136]
    __half* Bs = As + 128 * 136;            // [128][136]
    float*  Cs = (float*)dsm;               // [128][132] (overlay after compute)
    __shared__ float s_att[4][64];
    int tid = threadIdx.x;
    int bn = (g & 3) * 128, bm = (g >> 2) * 128;

    {
        int a = tid >> 6, j = tid & 63;
        int h = (bn >> 6) + (a & 1);
        s_att[a][j] = (a < 2) ? att_s[h * 64 + j] : att_d[h * 64 + j];
    }
    #pragma unroll
    for (int i = 0; i < 8; i++) {
        int idx = tid + i * 256;
        int r = idx >> 4, q = idx & 15;
        int gm = bm + r;
        uint4 v = (gm < NN) ? *(const uint4*)&g_xh[(size_t)gm * FIN + q * 8]
                            : make_uint4(0, 0, 0, 0);
        *(uint4*)&As[r * 136 + q * 8] = v;
    }
    #pragma unroll
    for (int i = 0; i < 8; i++) {
        int idx = tid + i * 256;
        int r = idx >> 4, q = idx & 15;
        *(uint4*)&Bs[r * 136 + q * 8] =
            *(const uint4*)&g_w1h[(size_t)r * C1 + bn + q * 8];
    }
    __syncthreads();

    int wid = tid >> 5;
    int wm = wid >> 2, wn = wid & 3;
    wmma::fragment<wmma::accumulator, 16, 16, 16, float> acc[4][2];
    #pragma unroll
    for (int i = 0; i < 4; i++)
        #pragma unroll
        for (int j = 0; j < 2; j++) wmma::fill_fragment(acc[i][j], 0.0f);

    #pragma unroll
    for (int kt = 0; kt < 8; kt++) {
        wmma::fragment<wmma::matrix_a, 16, 16, 16, __half, wmma::row_major> af[4];
        wmma::fragment<wmma::matrix_b, 16, 16, 16, __half, wmma::row_major> bf[2];
        #pragma unroll
        for (int i = 0; i < 4; i++)
            wmma::load_matrix_sync(af[i], As + (wm * 64 + i * 16) * 136 + kt * 16, 136);
        #pragma unroll
        for (int j = 0; j < 2; j++)
            wmma::load_matrix_sync(bf[j], Bs + (kt * 16) * 136 + wn * 32 + j * 16, 136);
        #pragma unroll
        for (int i = 0; i < 4; i++)
            #pragma unroll
            for (int j = 0; j < 2; j++)
                wmma::mma_sync(acc[i][j], af[i], bf[j], acc[i][j]);
    }
    __syncthreads();
    #pragma unroll
    for (int i = 0; i < 4; i++)
        #pragma unroll
        for (int j = 0; j < 2; j++)
            wmma::store_matrix_sync(Cs + (wm * 64 + i * 16) * 132 + wn * 32 + j * 16,
                                    acc[i][j], 132, wmma::mem_row_major);
    __syncthreads();

    int r = tid >> 1, half = tid & 1;
    int gm = bm + r;
    if (gm < NN) {
        int hglob = (bn >> 6) + half;
        const float* crow = Cs + r * 132 + half * 64;
        float sp = 0.f, dp = 0.f;
        #pragma unroll
        for (int q = 0; q < 8; q++) {
            float v[8];
            *(float4*)&v[0] = *(const float4*)&crow[q * 8];
            *(float4*)&v[4] = *(const float4*)&crow[q * 8 + 4];
            union { uint4 u; __half2 h[4]; } pk;
            pk.h[0] = __floats2half2_rn(v[0], v[1]);
            pk.h[1] = __floats2half2_rn(v[2], v[3]);
            pk.h[2] = __floats2half2_rn(v[4], v[5]);
            pk.h[3] = __floats2half2_rn(v[6], v[7]);
            *(uint4*)&g_h1h[(size_t)gm * C1 + bn + half * 64 + q * 8] = pk.u;
            #pragma unroll
            for (int jj = 0; jj < 8; jj++) {
                sp = fmaf(v[jj], s_att[half][q * 8 + jj], sp);
                dp = fmaf(v[jj], s_att[2 + half][q * 8 + jj], dp);
            }
        }
        g_as1[gm * H1 + hglob] = sp;
        g_ad1[gm * H1 + hglob] = dp;
    }
}

// ---------------- scatter || gemm1 (first half) ----------------------------
__global__ void __launch_bounds__(256, 2)
k_scatter_gemm1a(const int* __restrict__ ei,
                 const float* __restrict__ att_s, const float* __restrict__ att_d) {
    extern __shared__ char dsm[];
    if (blockIdx.x < G1_HALF) {
        gemm1_body(blockIdx.x, dsm, att_s, att_d);
    } else {
        int i = (blockIdx.x - G1_HALF) * 256 + threadIdx.x;
        if (i >= ET) return;
        int src, dst;
        if (i < EE) { src = ei[i]; dst = ei[EE + i]; }
        else        { src = i - EE; dst = i - EE; }
        int pos = g_rowptr[dst] + atomicAdd(&g_fill[dst], 1);
        g_esrc[pos] = src;
    }
}

// ---------------- sortseg (+re-zero g_fill) || gemm1 (second half) ---------
__global__ void __launch_bounds__(256, 2)
k_sortseg_gemm1b(const float* __restrict__ att_s, const float* __restrict__ att_d) {
    extern __shared__ char dsm[];
    if (blockIdx.x < G1_HALF) {
        gemm1_body(G1_HALF + blockIdx.x, dsm, att_s, att_d);
    } else {
        int d = (blockIdx.x - G1_HALF) * 256 + threadIdx.x;
        if (d >= NN) return;
        g_fill[d] = 0;                          // restore invariant
        int r0 = g_rowptr[d], r1 = g_rowptr[d + 1];
        int len = r1 - r0;
        if (len <= 1) return;
        if (len <= 64) {
            int buf[64];
            for (int i = 0; i < len; i++) buf[i] = g_esrc[r0 + i];
            for (int i = 1; i < len; i++) {
                int key = buf[i], j = i - 1;
                while (j >= 0 && buf[j] > key) { buf[j + 1] = buf[j]; j--; }
                buf[j + 1] = key;
            }
            for (int i = 0; i < len; i++) g_esrc[r0 + i] = buf[i];
        } else {
            for (int i = r0 + 1; i < r1; i++) {
                int key = g_esrc[i], j = i - 1;
                while (j >= r0 && g_esrc[j] > key) { g_esrc[j + 1] = g_esrc[j]; j--; }
                g_esrc[j + 1] = key;
            }
        }
    }
}

// ---------------- GEMM2 (tensor core) + att scores -------------------------
__global__ void __launch_bounds__(256, 2)
k_gemm2(const float* __restrict__ att_s, const float* __restrict__ att_d) {
    extern __shared__ char dsm[];
    __half* Asb = (__half*)dsm;             // 2 x [128][72]
    __half* Bsb = Asb + 2 * 128 * 72;       // 2 x [64][72]
    float*  Cs  = (float*)dsm;              // [128][68]
    __shared__ float s_att[2][64];
    int tid = threadIdx.x;
    int bm = blockIdx.x * 128;

    if (tid < 128) {
        int a = tid >> 6, j = tid & 63;
        s_att[a][j] = a ? att_d[j] : att_s[j];
    }
    #pragma unroll
    for (int i = 0; i < 4; i++) {
        int idx = tid + i * 256;
        int r = idx >> 3, q = idx & 7;
        int gm = bm + r;
        uint4 v = (gm < NN) ? *(const uint4*)&g_hah[(size_t)gm * C1 + q * 8]
                            : make_uint4(0, 0, 0, 0);
        *(uint4*)&Asb[r * 72 + q * 8] = v;
    }
    #pragma unroll
    for (int i = 0; i < 2; i++) {
        int idx = tid + i * 256;
        int r = idx >> 3, q = idx & 7;
        *(uint4*)&Bsb[r * 72 + q * 8] = *(const uint4*)&g_w2h[(size_t)r * HID + q * 8];
    }
    __syncthreads();

    int wid = tid >> 5;
    int wm = wid >> 1, wn = wid & 1;
    wmma::fragment<wmma::accumulator, 16, 16, 16, float> acc[2][2];
    #pragma unroll
    for (int i = 0; i < 2; i++)
        #pragma unroll
        for (int j = 0; j < 2; j++) wmma::fill_fragment(acc[i][j], 0.0f);

    for (int kt = 0; kt < 8; kt++) {
        int buf = kt & 1;
        uint4 pa[4], pb[2];
        if (kt < 7) {
            int k0 = (kt + 1) * 64;
            #pragma unroll
            for (int i = 0; i < 4; i++) {
                int idx = tid + i * 256;
                int r = idx >> 3, q = idx & 7;
                int gm = bm + r;
                pa[i] = (gm < NN) ? *(const uint4*)&g_hah[(size_t)gm * C1 + k0 + q * 8]
                                  : make_uint4(0, 0, 0, 0);
            }
            #pragma unroll
            for (int i = 0; i < 2; i++) {
                int idx = tid + i * 256;
                int r = idx >> 3, q = idx & 7;
                pb[i] = *(const uint4*)&g_w2h[(size_t)(k0 + r) * HID + q * 8];
            }
        }
        __half* As = Asb + buf * (128 * 72);
        __half* Bs = Bsb + buf * (64 * 72);
        #pragma unroll
        for (int ks = 0; ks < 4; ks++) {
            wmma::fragment<wmma::matrix_a, 16, 16, 16, __half, wmma::row_major> af[2];
            wmma::fragment<wmma::matrix_b, 16, 16, 16, __half, wmma::row_major> bf[2];
            #pragma unroll
            for (int i = 0; i < 2; i++)
                wmma::load_matrix_sync(af[i], As + (wm * 32 + i * 16) * 72 + ks * 16, 72);
            #pragma unroll
            for (int j = 0; j < 2; j++)
                wmma::load_matrix_sync(bf[j], Bs + (ks * 16) * 72 + wn * 32 + j * 16, 72);
            #pragma unroll
            for (int i = 0; i < 2; i++)
                #pragma unroll
                for (int j = 0; j < 2; j++)
                    wmma::mma_sync(acc[i][j], af[i], bf[j], acc[i][j]);
        }
        if (kt < 7) {
            int nb = buf ^ 1;
            __half* Asn = Asb + nb * (128 * 72);
            __half* Bsn = Bsb + nb * (64 * 72);
            #pragma unroll
            for (int i = 0; i < 4; i++) {
                int idx = tid + i * 256;
                int r = idx >> 3, q = idx & 7;
                *(uint4*)&Asn[r * 72 + q * 8] = pa[i];
            }
            #pragma unroll
            for (int i = 0; i < 2; i++) {
                int idx = tid + i * 256;
                int r = idx >> 3, q = idx & 7;
                *(uint4*)&Bsn[r * 72 + q * 8] = pb[i];
            }
            __syncthreads();
        }
    }
    __syncthreads();
    #pragma unroll
    for (int i = 0; i < 2; i++)
        #pragma unroll
        for (int j = 0; j < 2; j++)
            wmma::store_matrix_sync(Cs + (wm * 32 + i * 16) * 68 + wn * 32 + j * 16,
                                    acc[i][j], 68, wmma::mem_row_major);
    __syncthreads();

    int r = tid >> 1, half = tid & 1;
    int gm = bm + r;
    float sp = 0.f, dp = 0.f;
    if (gm < NN) {
        const float* crow = Cs + r * 68 + half * 32;
        #pragma unroll
        for (int q = 0; q < 4; q++) {
            float v[8];
            *(float4*)&v[0] = *(const float4*)&crow[q * 8];
            *(float4*)&v[4] = *(const float4*)&crow[q * 8 + 4];
            union { uint4 u; __half2 h[4]; } pk;
            pk.h[0] = __floats2half2_rn(v[0], v[1]);
            pk.h[1] = __floats2half2_rn(v[2], v[3]);
            pk.h[2] = __floats2half2_rn(v[4], v[5]);
            pk.h[3] = __floats2half2_rn(v[6], v[7]);
            *(uint4*)&g_h2h[(size_t)gm * HID + half * 32 + q * 8] = pk.u;
            #pragma unroll
            for (int jj = 0; jj < 8; jj++) {
                sp = fmaf(v[jj], s_att[0][half * 32 + q * 8 + jj], sp);
                dp = fmaf(v[jj], s_att[1][half * 32 + q * 8 + jj], dp);
            }
        }
    }
    sp += __shfl_xor_sync(0xffffffffu, sp, 1);
    dp += __shfl_xor_sync(0xffffffffu, dp, 1);
    if (gm < NN && half == 0) { g_as2[gm] = sp; g_ad2[gm] = dp; }
}

__device__ __forceinline__ float lrelu(float e) {
    return e > 0.f ? e : NEG_SLOPE * e;
}

// ---------------- gather1: block per dst, warp h = head h ------------------
__global__ void __launch_bounds__(256, 8)
k_gather1(const float* __restrict__ bias) {
    int d = blockIdx.x;
    int h = threadIdx.x >> 5, lane = threadIdx.x & 31;
    int r0 = g_rowptr[d], r1 = g_rowptr[d + 1];
    float ad = g_ad1[d * H1 + h];

    float denp = 0.f, a0 = 0.f, a1 = 0.f;
    for (int base = r0; base < r1; base += 32) {
        int n = min(32, r1 - base);
        int sv = 0; float w = 0.f;
        if (base + lane < r1) {
            sv = __ldg(&g_esrc[base + lane]);
            float e = lrelu(__ldg(&g_as1[sv * H1 + h]) + ad);
            w = __expf(e);
        }
        denp += w;
        #pragma unroll 4
        for (int j = 0; j < n; j++) {
            int   s  = __shfl_sync(0xffffffffu, sv, j);
            float wj = __shfl_sync(0xffffffffu, w, j);
            __half2 v = ((const __half2*)(g_h1h + (size_t)s * C1 + h * HID))[lane];
            float2 vf = __half22float2(v);
            a0 = fmaf(wj, vf.x, a0);
            a1 = fmaf(wj, vf.y, a1);
        }
    }
    float den = denp;
    #pragma unroll
    for (int off = 16; off; off >>= 1) den += __shfl_xor_sync(0xffffffffu, den, off);

    float inv = 1.f / (den + EPS);
    int c0 = h * HID + 2 * lane;
    float o0 = a0 * inv + bias[c0];
    float o1 = a1 * inv + bias[c0 + 1];
    o0 = o0 > 0.f ? o0 : expm1f(o0);
    o1 = o1 > 0.f ? o1 : expm1f(o1);
    *(__half2*)&g_hah[(size_t)d * C1 + c0] = __floats2half2_rn(o0, o1);
}

// ---------------- gather2: warp per dst ------------------------------------
__global__ void __launch_bounds__(256, 8)
k_gather2(const float* __restrict__ bias) {
    int d = (blockIdx.x * blockDim.x + threadIdx.x) >> 5;
    int lane = threadIdx.x & 31;
    if (d >= NN) return;
    float ad = g_ad2[d];
    int r0 = g_rowptr[d], r1 = g_rowptr[d + 1];

    float denp = 0.f, a0 = 0.f, a1 = 0.f;
    for (int base = r0; base < r1; base += 32) {
        int n = min(32, r1 - base);
        int sv = 0; float w = 0.f;
        if (base + lane < r1) {
            sv = __ldg(&g_esrc[base + lane]);
            float e = lrelu(__ldg(&g_as2[sv]) + ad);
            w = __expf(e);
        }
        denp += w;
        #pragma unroll 4
        for (int j = 0; j < n; j++) {
            int   s  = __shfl_sync(0xffffffffu, sv, j);
            float wj = __shfl_sync(0xffffffffu, w, j);
            __half2 v = ((const __half2*)(g_h2h + (size_t)s * HID))[lane];
            float2 vf = __half22float2(v);
            a0 = fmaf(wj, vf.x, a0);
            a1 = fmaf(wj, vf.y, a1);
        }
    }
    float den = denp;
    #pragma unroll
    for (int off = 16; off; off >>= 1) den += __shfl_xor_sync(0xffffffffu, den, off);

    float inv = 1.f / (den + EPS);
    int c0 = 2 * lane;
    g_out2[(size_t)d * HID + c0]     = a0 * inv + bias[c0];
    g_out2[(size_t)d * HID + c0 + 1] = a1 * inv + bias[c0 + 1];
}

// ---------------- global mean pool + final linear ----------------
__device__ __forceinline__ int lb32(const int* a, int n, int v) {
    int lo = 0, hi = n;
    while (lo < hi) { int mid = (lo + hi) >> 1; if (a[mid] < v) lo = mid + 1; else hi = mid; }
    return lo;
}

__global__ void k_pool(const int* __restrict__ batch,
                       const float* __restrict__ linW,
                       const float* __restrict__ linb,
                       float* __restrict__ out) {
    __shared__ float sm[256];
    int g = blockIdx.x;
    int lo = lb32(batch, NN, g);
    int hi = lb32(batch, NN, g + 1);
    int c = threadIdx.x & 63;
    int sub = threadIdx.x >> 6;
    float acc = 0.f;
    for (int n = lo + sub; n < hi; n += 4)
        acc += g_out2[(size_t)n * HID + c];
    sm[threadIdx.x] = acc;
    __syncthreads();
    if (threadIdx.x < 64) {
        float v = sm[threadIdx.x] + sm[threadIdx.x + 64] + sm[threadIdx.x + 128] + sm[threadIdx.x + 192];
        sm[threadIdx.x] = v * linW[threadIdx.x];
    }
    __syncthreads();
    if (threadIdx.x < 32) {
        float v = sm[threadIdx.x] + sm[threadIdx.x + 32];
        #pragma unroll
        for (int off = 16; off; off >>= 1) v += __shfl_down_sync(0xffffffffu, v, off);
        if (threadIdx.x == 0) {
            float cnt = (float)(hi - lo);
            out[g] = v / fmaxf(cnt, 1.f) + linb[0];
        }
    }
}

// ---------------- launch ----------------
extern "C" void kernel_launch(void* const* d_in, const int* in_sizes, int n_in,
                              void* d_out, int out_size) {
    const float* x     = (const float*)d_in[0];
    const int*   ei    = (const int*)d_in[1];
    const int*   batch = (const int*)d_in[2];
    const float* W1   = (const float*)d_in[3];
    const float* as1  = (const float*)d_in[4];
    const float* ad1  = (const float*)d_in[5];
    const float* b1   = (const float*)d_in[6];
    const float* W2   = (const float*)d_in[7];
    const float* as2  = (const float*)d_in[8];
    const float* ad2  = (const float*)d_in[9];
    const float* b2   = (const float*)d_in[10];
    const float* linW = (const float*)d_in[11];
    const float* linb = (const float*)d_in[12];
    float* out = (float*)d_out;
    (void)in_sizes; (void)n_in; (void)out_size;

    cudaFuncSetAttribute(k_scatter_gemm1a, cudaFuncAttributeMaxDynamicSharedMemorySize, 69632);
    cudaFuncSetAttribute(k_sortseg_gemm1b, cudaFuncAttributeMaxDynamicSharedMemorySize, 69632);
    cudaFuncSetAttribute(k_gemm2, cudaFuncAttributeMaxDynamicSharedMemorySize, 55296);

    // CSR count (g_deg zeroed invariant maintained by scan_a of prior call /
    // static zero-init on first call)
    k_count<<<(ET + 255) / 256, 256>>>(ei);
    // scan_a (+re-zero g_deg) || x->fp16
    k_scanA_cvtx<<<SCAN_NB + CVTX_BLOCKS, 1024>>>(x);
    // scan_b || W->fp16
    k_scanB_cvtw<<<1 + 48, 256>>>(W1, W2);
    k_scan_c<<<SCAN_NB, SCAN_B>>>();
    // scatter || gemm1 first half
    k_scatter_gemm1a<<<G1_HALF + SCAT_BLOCKS, 256, 69632>>>(ei, as1, ad1);
    // sortseg (+re-zero g_fill) || gemm1 second half
    k_sortseg_gemm1b<<<G1_HALF + SORT_BLOCKS, 256, 69632>>>(as1, ad1);

    k_gather1<<<NN, 256>>>(b1);

    k_gemm2<<<(NN + 127) / 128, 256, 55296>>>(as2, ad2);
    k_gather2<<<(NN + 7) / 8, 256>>>(b2);

    k_pool<<<GG, 256>>>(batch, linW, linb, out);
}

// round 15
// speedup vs baseline: 1.0726x; 1.0726x over previous
#include <cuda_runtime.h>
#include <cuda_fp16.h>
#include <mma.h>
#include <math.h>

using namespace nvcuda;

#define NN 50000
#define EE 800000
#define ET (EE + NN)
#define FIN 128
#define HID 64
#define H1 8
#define C1 (H1 * HID)   // 512
#define GG 64
#define NEG_SLOPE 0.2f
#define EPS 1e-16f
#define SCAN_B 1024
#define SCAN_NB ((NN + SCAN_B - 1) / SCAN_B)   // 49

#define CNT_BLOCKS ((ET + 255) / 256)                 // 3321
#define CVTX_ITEMS (NN * FIN / 8)                     // 800000
#define CVTX_BLOCKS ((CVTX_ITEMS + 255) / 256)        // 3125
#define CVTW_ITEMS (FIN * C1 / 8 + C1 * HID / 8)      // 12288
#define CVTW_BLOCKS ((CVTW_ITEMS + 255) / 256)        // 48

// ---------------- scratch (device globals; no allocations allowed) ----------
__device__ __half g_xh[(size_t)NN * FIN];
__device__ __half g_w1h[FIN * C1];
__device__ __half g_w2h[C1 * HID];
__device__ __half g_h1h[(size_t)NN * C1];
__device__ __half g_hah[(size_t)NN * C1];
__device__ __half g_h2h[(size_t)NN * HID];
__device__ float  g_as1[NN * H1];
__device__ float  g_ad1[NN * H1];
__device__ float  g_as2[NN];
__device__ float  g_ad2[NN];
__device__ float  g_out2[NN * HID];
__device__ int    g_deg[NN];     // zeroed at load; re-zeroed by scan_a each call
__device__ int    g_fill[NN];    // zeroed at load; re-zeroed by sortseg each call
__device__ int    g_rowptr[NN + 1];
__device__ int    g_part[64];
__device__ int    g_esrc[ET];

// ---------------- fused: count || x->fp16 || W->fp16 (no smem, 256 thr) ----
__global__ void k_count_cvt(const int* __restrict__ ei, const float* __restrict__ x,
                            const float* __restrict__ W1, const float* __restrict__ W2) {
    int b = blockIdx.x;
    if (b < CNT_BLOCKS) {
        int i = b * 256 + threadIdx.x;
        if (i >= ET) return;
        int dst = (i < EE) ? ei[EE + i] : (i - EE);
        atomicAdd(&g_deg[dst], 1);
    } else if (b < CNT_BLOCKS + CVTX_BLOCKS) {
        int i = (b - CNT_BLOCKS) * 256 + threadIdx.x;
        if (i >= CVTX_ITEMS) return;
        const float4* p = (const float4*)x + (size_t)i * 2;
        float4 a = p[0], c = p[1];
        union { uint4 u; __half2 h[4]; } pk;
        pk.h[0] = __floats2half2_rn(a.x, a.y);
        pk.h[1] = __floats2half2_rn(a.z, a.w);
        pk.h[2] = __floats2half2_rn(c.x, c.y);
        pk.h[3] = __floats2half2_rn(c.z, c.w);
        ((uint4*)g_xh)[i] = pk.u;
    } else {
        int i = (b - CNT_BLOCKS - CVTX_BLOCKS) * 256 + threadIdx.x;
        const int n1 = FIN * C1 / 8;
        if (i >= CVTW_ITEMS) return;
        const float* src; __half* dst; int j;
        if (i < n1) { src = W1; dst = g_w1h; j = i; }
        else        { src = W2; dst = g_w2h; j = i - n1; }
        const float4* p = (const float4*)src + (size_t)j * 2;
        float4 a = p[0], c = p[1];
        union { uint4 u; __half2 h[4]; } pk;
        pk.h[0] = __floats2half2_rn(a.x, a.y);
        pk.h[1] = __floats2half2_rn(a.z, a.w);
        pk.h[2] = __floats2half2_rn(c.x, c.y);
        pk.h[3] = __floats2half2_rn(c.z, c.w);
        ((uint4*)dst)[j] = pk.u;
    }
}

// ---------------- 3-phase exclusive scan of g_deg -> g_rowptr ---------------
__global__ void k_scan_a() {
    __shared__ int s[SCAN_B];
    int i = blockIdx.x * SCAN_B + threadIdx.x;
    int v = (i < NN) ? g_deg[i] : 0;
    if (i < NN) g_deg[i] = 0;                   // restore invariant
    s[threadIdx.x] = v;
    __syncthreads();
    #pragma unroll
    for (int off = 1; off < SCAN_B; off <<= 1) {
        int t = (threadIdx.x >= off) ? s[threadIdx.x - off] : 0;
        __syncthreads();
        s[threadIdx.x] += t;
        __syncthreads();
    }
    if (i < NN) g_rowptr[i] = s[threadIdx.x] - v;
    if (threadIdx.x == SCAN_B - 1) g_part[blockIdx.x] = s[SCAN_B - 1];
}

__global__ void k_scan_b() {
    int lane = threadIdx.x;                      // 0..31
    int v0 = (lane < SCAN_NB) ? g_part[lane] : 0;
    int v1 = (lane + 32 < SCAN_NB) ? g_part[lane + 32] : 0;
    int x0 = v0;
    #pragma unroll
    for (int off = 1; off < 32; off <<= 1) {
        int t = __shfl_up_sync(0xffffffffu, x0, off);
        if (lane >= off) x0 += t;
    }
    int total0 = __shfl_sync(0xffffffffu, x0, 31);
    int x1 = v1;
    #pragma unroll
    for (int off = 1; off < 32; off <<= 1) {
        int t = __shfl_up_sync(0xffffffffu, x1, off);
        if (lane >= off) x1 += t;
    }
    x1 += total0;
    if (lane < SCAN_NB) g_part[lane] = x0 - v0;
    if (lane + 32 < SCAN_NB) g_part[lane + 32] = x1 - v1;
    if (lane == 31) g_rowptr[NN] = x1;
}

__global__ void k_scan_c() {
    int i = blockIdx.x * SCAN_B + threadIdx.x;
    if (i < NN) g_rowptr[i] += g_part[blockIdx.x];
}

__global__ void k_scatter(const int* __restrict__ ei) {
    int i = blockIdx.x * blockDim.x + threadIdx.x;
    if (i >= ET) return;
    int src, dst;
    if (i < EE) { src = ei[i]; dst = ei[EE + i]; }
    else        { src = i - EE; dst = i - EE; }
    int pos = g_rowptr[dst] + atomicAdd(&g_fill[dst], 1);
    g_esrc[pos] = src;
}

__global__ void k_sortseg() {
    int d = blockIdx.x * blockDim.x + threadIdx.x;
    if (d >= NN) return;
    g_fill[d] = 0;                               // restore invariant
    int r0 = g_rowptr[d], r1 = g_rowptr[d + 1];
    int len = r1 - r0;
    if (len <= 1) return;
    if (len <= 64) {
        int buf[64];
        for (int i = 0; i < len; i++) buf[i] = g_esrc[r0 + i];
        for (int i = 1; i < len; i++) {
            int key = buf[i], j = i - 1;
            while (j >= 0 && buf[j] > key) { buf[j + 1] = buf[j]; j--; }
            buf[j + 1] = key;
        }
        for (int i = 0; i < len; i++) g_esrc[r0 + i] = buf[i];
    } else {
        for (int i = r0 + 1; i < r1; i++) {
            int key = g_esrc[i], j = i - 1;
            while (j >= r0 && g_esrc[j] > key) { g_esrc[j + 1] = g_esrc[j]; j--; }
            g_esrc[j + 1] = key;
        }
    }
}

// ---------------- GEMM1 (tensor core) + att scores -------------------------
__global__ void __launch_bounds__(256, 2)
k_gemm1(const float* __restrict__ att_s, const float* __restrict__ att_d) {
    extern __shared__ char dsm[];
    __half* As = (__half*)dsm;              // [128][136]
    __half* Bs = As + 128 * 136;            // [128][136]
    float*  Cs = (float*)dsm;               // [128][132] (overlay after compute)
    __shared__ float s_att[4][64];
    int tid = threadIdx.x;
    int bm = blockIdx.y * 128, bn = blockIdx.x * 128;

    {
        int a = tid >> 6, j = tid & 63;
        int h = (bn >> 6) + (a & 1);
        s_att[a][j] = (a < 2) ? att_s[h * 64 + j] : att_d[h * 64 + j];
    }
    #pragma unroll
    for (int i = 0; i < 8; i++) {
        int idx = tid + i * 256;
        int r = idx >> 4, q = idx & 15;
        int gm = bm + r;
        uint4 v = (gm < NN) ? *(const uint4*)&g_xh[(size_t)gm * FIN + q * 8]
                            : make_uint4(0, 0, 0, 0);
        *(uint4*)&As[r * 136 + q * 8] = v;
    }
    #pragma unroll
    for (int i = 0; i < 8; i++) {
        int idx = tid + i * 256;
        int r = idx >> 4, q = idx & 15;
        *(uint4*)&Bs[r * 136 + q * 8] =
            *(const uint4*)&g_w1h[(size_t)r * C1 + bn + q * 8];
    }
    __syncthreads();

    int wid = tid >> 5;
    int wm = wid >> 2, wn = wid & 3;
    wmma::fragment<wmma::accumulator, 16, 16, 16, float> acc[4][2];
    #pragma unroll
    for (int i = 0; i < 4; i++)
        #pragma unroll
        for (int j = 0; j < 2; j++) wmma::fill_fragment(acc[i][j], 0.0f);

    #pragma unroll
    for (int kt = 0; kt < 8; kt++) {
        wmma::fragment<wmma::matrix_a, 16, 16, 16, __half, wmma::row_major> af[4];
        wmma::fragment<wmma::matrix_b, 16, 16, 16, __half, wmma::row_major> bf[2];
        #pragma unroll
        for (int i = 0; i < 4; i++)
            wmma::load_matrix_sync(af[i], As + (wm * 64 + i * 16) * 136 + kt * 16, 136);
        #pragma unroll
        for (int j = 0; j < 2; j++)
            wmma::load_matrix_sync(bf[j], Bs + (kt * 16) * 136 + wn * 32 + j * 16, 136);
        #pragma unroll
        for (int i = 0; i < 4; i++)
            #pragma unroll
            for (int j = 0; j < 2; j++)
                wmma::mma_sync(acc[i][j], af[i], bf[j], acc[i][j]);
    }
    __syncthreads();
    #pragma unroll
    for (int i = 0; i < 4; i++)
        #pragma unroll
        for (int j = 0; j < 2; j++)
            wmma::store_matrix_sync(Cs + (wm * 64 + i * 16) * 132 + wn * 32 + j * 16,
                                    acc[i][j], 132, wmma::mem_row_major);
    __syncthreads();

    int r = tid >> 1, half = tid & 1;
    int gm = bm + r;
    if (gm < NN) {
        int hglob = (bn >> 6) + half;
        const float* crow = Cs + r * 132 + half * 64;
        float sp = 0.f, dp = 0.f;
        #pragma unroll
        for (int q = 0; q < 8; q++) {
            float v[8];
            *(float4*)&v[0] = *(const float4*)&crow[q * 8];
            *(float4*)&v[4] = *(const float4*)&crow[q * 8 + 4];
            union { uint4 u; __half2 h[4]; } pk;
            pk.h[0] = __floats2half2_rn(v[0], v[1]);
            pk.h[1] = __floats2half2_rn(v[2], v[3]);
            pk.h[2] = __floats2half2_rn(v[4], v[5]);
            pk.h[3] = __floats2half2_rn(v[6], v[7]);
            *(uint4*)&g_h1h[(size_t)gm * C1 + bn + half * 64 + q * 8] = pk.u;
            #pragma unroll
            for (int jj = 0; jj < 8; jj++) {
                sp = fmaf(v[jj], s_att[half][q * 8 + jj], sp);
                dp = fmaf(v[jj], s_att[2 + half][q * 8 + jj], dp);
            }
        }
        g_as1[gm * H1 + hglob] = sp;
        g_ad1[gm * H1 + hglob] = dp;
    }
}

// ---------------- GEMM2 (tensor core) + att scores -------------------------
__global__ void __launch_bounds__(256, 2)
k_gemm2(const float* __restrict__ att_s, const float* __restrict__ att_d) {
    extern __shared__ char dsm[];
    __half* Asb = (__half*)dsm;             // 2 x [128][72]
    __half* Bsb = Asb + 2 * 128 * 72;       // 2 x [64][72]
    float*  Cs  = (float*)dsm;              // [128][68]
    __shared__ float s_att[2][64];
    int tid = threadIdx.x;
    int bm = blockIdx.x * 128;

    if (tid < 128) {
        int a = tid >> 6, j = tid & 63;
        s_att[a][j] = a ? att_d[j] : att_s[j];
    }
    #pragma unroll
    for (int i = 0; i < 4; i++) {
        int idx = tid + i * 256;
        int r = idx >> 3, q = idx & 7;
        int gm = bm + r;
        uint4 v = (gm < NN) ? *(const uint4*)&g_hah[(size_t)gm * C1 + q * 8]
                            : make_uint4(0, 0, 0, 0);
        *(uint4*)&Asb[r * 72 + q * 8] = v;
    }
    #pragma unroll
    for (int i = 0; i < 2; i++) {
        int idx = tid + i * 256;
        int r = idx >> 3, q = idx & 7;
        *(uint4*)&Bsb[r * 72 + q * 8] = *(const uint4*)&g_w2h[(size_t)r * HID + q * 8];
    }
    __syncthreads();

    int wid = tid >> 5;
    int wm = wid >> 1, wn = wid & 1;
    wmma::fragment<wmma::accumulator, 16, 16, 16, float> acc[2][2];
    #pragma unroll
    for (int i = 0; i < 2; i++)
        #pragma unroll
        for (int j = 0; j < 2; j++) wmma::fill_fragment(acc[i][j], 0.0f);

    for (int kt = 0; kt < 8; kt++) {
        int buf = kt & 1;
        uint4 pa[4], pb[2];
        if (kt < 7) {
            int k0 = (kt + 1) * 64;
            #pragma unroll
            for (int i = 0; i < 4; i++) {
                int idx = tid + i * 256;
                int r = idx >> 3, q = idx & 7;
                int gm = bm + r;
                pa[i] = (gm < NN) ? *(const uint4*)&g_hah[(size_t)gm * C1 + k0 + q * 8]
                                  : make_uint4(0, 0, 0, 0);
            }
            #pragma unroll
            for (int i = 0; i < 2; i++) {
                int idx = tid + i * 256;
                int r = idx >> 3, q = idx & 7;
                pb[i] = *(const uint4*)&g_w2h[(size_t)(k0 + r) * HID + q * 8];
            }
        }
        __half* As = Asb + buf * (128 * 72);
        __half* Bs = Bsb + buf * (64 * 72);
        #pragma unroll
        for (int ks = 0; ks < 4; ks++) {
            wmma::fragment<wmma::matrix_a, 16, 16, 16, __half, wmma::row_major> af[2];
            wmma::fragment<wmma::matrix_b, 16, 16, 16, __half, wmma::row_major> bf[2];
            #pragma unroll
            for (int i = 0; i < 2; i++)
                wmma::load_matrix_sync(af[i], As + (wm * 32 + i * 16) * 72 + ks * 16, 72);
            #pragma unroll
            for (int j = 0; j < 2; j++)
                wmma::load_matrix_sync(bf[j], Bs + (ks * 16) * 72 + wn * 32 + j * 16, 72);
            #pragma unroll
            for (int i = 0; i < 2; i++)
                #pragma unroll
                for (int j = 0; j < 2; j++)
                    wmma::mma_sync(acc[i][j], af[i], bf[j], acc[i][j]);
        }
        if (kt < 7) {
            int nb = buf ^ 1;
            __half* Asn = Asb + nb * (128 * 72);
            __half* Bsn = Bsb + nb * (64 * 72);
            #pragma unroll
            for (int i = 0; i < 4; i++) {
                int idx = tid + i * 256;
                int r = idx >> 3, q = idx & 7;
                *(uint4*)&Asn[r * 72 + q * 8] = pa[i];
            }
            #pragma unroll
            for (int i = 0; i < 2; i++) {
                int idx = tid + i * 256;
                int r = idx >> 3, q = idx & 7;
                *(uint4*)&Bsn[r * 72 + q * 8] = pb[i];
            }
            __syncthreads();
        }
    }
    __syncthreads();
    #pragma unroll
    for (int i = 0; i < 2; i++)
        #pragma unroll
        for (int j = 0; j < 2; j++)
            wmma::store_matrix_sync(Cs + (wm * 32 + i * 16) * 68 + wn * 32 + j * 16,
                                    acc[i][j], 68, wmma::mem_row_major);
    __syncthreads();

    int r = tid >> 1, half = tid & 1;
    int gm = bm + r;
    float sp = 0.f, dp = 0.f;
    if (gm < NN) {
        const float* crow = Cs + r * 68 + half * 32;
        #pragma unroll
        for (int q = 0; q < 4; q++) {
            float v[8];
            *(float4*)&v[0] = *(const float4*)&crow[q * 8];
            *(float4*)&v[4] = *(const float4*)&crow[q * 8 + 4];
            union { uint4 u; __half2 h[4]; } pk;
            pk.h[0] = __floats2half2_rn(v[0], v[1]);
            pk.h[1] = __floats2half2_rn(v[2], v[3]);
            pk.h[2] = __floats2half2_rn(v[4], v[5]);
            pk.h[3] = __floats2half2_rn(v[6], v[7]);
            *(uint4*)&g_h2h[(size_t)gm * HID + half * 32 + q * 8] = pk.u;
            #pragma unroll
            for (int jj = 0; jj < 8; jj++) {
                sp = fmaf(v[jj], s_att[0][half * 32 + q * 8 + jj], sp);
                dp = fmaf(v[jj], s_att[1][half * 32 + q * 8 + jj], dp);
            }
        }
    }
    sp += __shfl_xor_sync(0xffffffffu, sp, 1);
    dp += __shfl_xor_sync(0xffffffffu, dp, 1);
    if (gm < NN && half == 0) { g_as2[gm] = sp; g_ad2[gm] = dp; }
}

__device__ __forceinline__ float lrelu(float e) {
    return e > 0.f ? e : NEG_SLOPE * e;
}

// ---------------- gather1: block per dst, warp h = head h ------------------
__global__ void __launch_bounds__(256, 8)
k_gather1(const float* __restrict__ bias) {
    int d = blockIdx.x;
    int h = threadIdx.x >> 5, lane = threadIdx.x & 31;
    int r0 = g_rowptr[d], r1 = g_rowptr[d + 1];
    float ad = g_ad1[d * H1 + h];

    float denp = 0.f, a0 = 0.f, a1 = 0.f;
    for (int base = r0; base < r1; base += 32) {
        int n = min(32, r1 - base);
        int sv = 0; float w = 0.f;
        if (base + lane < r1) {
            sv = __ldg(&g_esrc[base + lane]);
            float e = lrelu(__ldg(&g_as1[sv * H1 + h]) + ad);
            w = __expf(e);
        }
        denp += w;
        #pragma unroll 8
        for (int j = 0; j < n; j++) {
            int   s  = __shfl_sync(0xffffffffu, sv, j);
            float wj = __shfl_sync(0xffffffffu, w, j);
            __half2 v = ((const __half2*)(g_h1h + (size_t)s * C1 + h * HID))[lane];
            float2 vf = __half22float2(v);
            a0 = fmaf(wj, vf.x, a0);
            a1 = fmaf(wj, vf.y, a1);
        }
    }
    float den = denp;
    #pragma unroll
    for (int off = 16; off; off >>= 1) den += __shfl_xor_sync(0xffffffffu, den, off);

    float inv = 1.f / (den + EPS);
    int c0 = h * HID + 2 * lane;
    float o0 = a0 * inv + bias[c0];
    float o1 = a1 * inv + bias[c0 + 1];
    o0 = o0 > 0.f ? o0 : expm1f(o0);
    o1 = o1 > 0.f ? o1 : expm1f(o1);
    *(__half2*)&g_hah[(size_t)d * C1 + c0] = __floats2half2_rn(o0, o1);
}

// ---------------- gather2: warp per dst ------------------------------------
__global__ void __launch_bounds__(256, 8)
k_gather2(const float* __restrict__ bias) {
    int d = (blockIdx.x * blockDim.x + threadIdx.x) >> 5;
    int lane = threadIdx.x & 31;
    if (d >= NN) return;
    float ad = g_ad2[d];
    int r0 = g_rowptr[d], r1 = g_rowptr[d + 1];

    float denp = 0.f, a0 = 0.f, a1 = 0.f;
    for (int base = r0; base < r1; base += 32) {
        int n = min(32, r1 - base);
        int sv = 0; float w = 0.f;
        if (base + lane < r1) {
            sv = __ldg(&g_esrc[base + lane]);
            float e = lrelu(__ldg(&g_as2[sv]) + ad);
            w = __expf(e);
        }
        denp += w;
        #pragma unroll 8
        for (int j = 0; j < n; j++) {
            int   s  = __shfl_sync(0xffffffffu, sv, j);
            float wj = __shfl_sync(0xffffffffu, w, j);
            __half2 v = ((const __half2*)(g_h2h + (size_t)s * HID))[lane];
            float2 vf = __half22float2(v);
            a0 = fmaf(wj, vf.x, a0);
            a1 = fmaf(wj, vf.y, a1);
        }
    }
    float den = denp;
    #pragma unroll
    for (int off = 16; off; off >>= 1) den += __shfl_xor_sync(0xffffffffu, den, off);

    float inv = 1.f / (den + EPS);
    int c0 = 2 * lane;
    g_out2[(size_t)d * HID + c0]     = a0 * inv + bias[c0];
    g_out2[(size_t)d * HID + c0 + 1] = a1 * inv + bias[c0 + 1];
}

// ---------------- global mean pool + final linear ----------------
__device__ __forceinline__ int lb32(const int* a, int n, int v) {
    int lo = 0, hi = n;
    while (lo < hi) { int mid = (lo + hi) >> 1; if (a[mid] < v) lo = mid + 1; else hi = mid; }
    return lo;
}

__global__ void k_pool(const int* __restrict__ batch,
                       const float* __restrict__ linW,
                       const float* __restrict__ linb,
                       float* __restrict__ out) {
    __shared__ float sm[256];
    int g = blockIdx.x;
    int lo = lb32(batch, NN, g);
    int hi = lb32(batch, NN, g + 1);
    int c = threadIdx.x & 63;
    int sub = threadIdx.x >> 6;
    float acc = 0.f;
    for (int n = lo + sub; n < hi; n += 4)
        acc += g_out2[(size_t)n * HID + c];
    sm[threadIdx.x] = acc;
    __syncthreads();
    if (threadIdx.x < 64) {
        float v = sm[threadIdx.x] + sm[threadIdx.x + 64] + sm[threadIdx.x + 128] + sm[threadIdx.x + 192];
        sm[threadIdx.x] = v * linW[threadIdx.x];
    }
    __syncthreads();
    if (threadIdx.x < 32) {
        float v = sm[threadIdx.x] + sm[threadIdx.x + 32];
        #pragma unroll
        for (int off = 16; off; off >>= 1) v += __shfl_down_sync(0xffffffffu, v, off);
        if (threadIdx.x == 0) {
            float cnt = (float)(hi - lo);
            out[g] = v / fmaxf(cnt, 1.f) + linb[0];
        }
    }
}

// ---------------- launch ----------------
extern "C" void kernel_launch(void* const* d_in, const int* in_sizes, int n_in,
                              void* d_out, int out_size) {
    const float* x     = (const float*)d_in[0];
    const int*   ei    = (const int*)d_in[1];
    const int*   batch = (const int*)d_in[2];
    const float* W1   = (const float*)d_in[3];
    const float* as1  = (const float*)d_in[4];
    const float* ad1  = (const float*)d_in[5];
    const float* b1   = (const float*)d_in[6];
    const float* W2   = (const float*)d_in[7];
    const float* as2  = (const float*)d_in[8];
    const float* ad2  = (const float*)d_in[9];
    const float* b2   = (const float*)d_in[10];
    const float* linW = (const float*)d_in[11];
    const float* linb = (const float*)d_in[12];
    float* out = (float*)d_out;
    (void)in_sizes; (void)n_in; (void)out_size;

    cudaFuncSetAttribute(k_gemm1, cudaFuncAttributeMaxDynamicSharedMemorySize, 69632);
    cudaFuncSetAttribute(k_gemm2, cudaFuncAttributeMaxDynamicSharedMemorySize, 55296);

    // count || x->fp16 || W->fp16 (homogeneous no-smem blocks)
    k_count_cvt<<<CNT_BLOCKS + CVTX_BLOCKS + CVTW_BLOCKS, 256>>>(ei, x, W1, W2);
    k_scan_a<<<SCAN_NB, SCAN_B>>>();
    k_scan_b<<<1, 32>>>();
    k_scan_c<<<SCAN_NB, SCAN_B>>>();
    k_scatter<<<(ET + 255) / 256, 256>>>(ei);
    k_sortseg<<<(NN + 255) / 256, 256>>>();

    // layer 1
    {
        dim3 grid(C1 / 128, (NN + 127) / 128);
        k_gemm1<<<grid, 256, 69632>>>(as1, ad1);
    }
    k_gather1<<<NN, 256>>>(b1);

    // layer 2
    k_gemm2<<<(NN + 127) / 128, 256, 55296>>>(as2, ad2);
    k_gather2<<<(NN + 7) / 8, 256>>>(b2);

    k_pool<<<GG, 256>>>(batch, linW, linb, out);
}